// round 3
// baseline (speedup 1.0000x reference)
#include <cuda_runtime.h>
#include <cuda_bf16.h>

#define NN 50000
#define EE 800000
#define DD 128
#define NG 64

// -------- scratch (device globals: no allocation allowed) --------
__device__ __align__(16) float g_tmp[NN * DD];   // h @ W result
__device__ __align__(16) float g_h[NN * DD];     // aggregated layer output
__device__ __align__(16) float g_dinv[NN];       // degree -> rsqrt(degree)
__device__ __align__(16) float g_cnt[NG];        // pool counts

// ================= degree computation =================
__global__ void k_deg_init() {
    int i = blockIdx.x * blockDim.x + threadIdx.x;
    if (i < NN) g_dinv[i] = 1.0f;  // self loop contributes 1
}

__global__ void k_deg_count(const int* __restrict__ ei) {
    int e = blockIdx.x * blockDim.x + threadIdx.x;
    if (e < EE) {
        int d = ei[EE + e];   // dst row
        atomicAdd(&g_dinv[d], 1.0f);
    }
}

__global__ void k_deg_rsqrt() {
    int i = blockIdx.x * blockDim.x + threadIdx.x;
    if (i < NN) g_dinv[i] = rsqrtf(g_dinv[i]);  // deg >= 1 always (self loop)
}

// ================= GEMM: C[M,128] = reluOpt(A)[M,128] @ W[128,128] =================
// 128x128 tile per block, 256 threads, 8x8 micro-tile per thread,
// packed fp32 pairs via fma.rn.f32x2 (2x fp32 throughput on sm_103a).
__global__ __launch_bounds__(256, 2)
void k_gemm(const float* __restrict__ A, const float* __restrict__ W,
            float* __restrict__ C, int M, int relu_in) {
    __shared__ float As[16][128];   // [k][row]  (transposed tile)
    __shared__ float Ws[16][128];   // [k][col]

    int tid = threadIdx.x;
    int tx = tid & 15;        // col group
    int ty = tid >> 4;        // row group
    int row0 = blockIdx.x * 128;

    unsigned long long acc[8][4];   // 8 rows x 8 cols as 4 f32x2 pairs
#pragma unroll
    for (int i = 0; i < 8; i++)
#pragma unroll
        for (int j = 0; j < 4; j++) acc[i][j] = 0ull;

    for (int kt = 0; kt < 8; kt++) {
        // load A tile: 16 k-cols x 128 rows, store transposed
#pragma unroll
        for (int q = 0; q < 2; q++) {
            int id = tid + q * 256;          // 0..511 float4 slots
            int r = id >> 2;                 // row within tile
            int kc = (id & 3) * 4;           // k within tile
            int grow = row0 + r;
            float4 v = make_float4(0.f, 0.f, 0.f, 0.f);
            if (grow < M) v = *(const float4*)&A[(size_t)grow * DD + kt * 16 + kc];
            if (relu_in) {
                v.x = fmaxf(v.x, 0.f); v.y = fmaxf(v.y, 0.f);
                v.z = fmaxf(v.z, 0.f); v.w = fmaxf(v.w, 0.f);
            }
            As[kc + 0][r] = v.x; As[kc + 1][r] = v.y;
            As[kc + 2][r] = v.z; As[kc + 3][r] = v.w;
        }
        // load W tile: contiguous copy
#pragma unroll
        for (int q = 0; q < 2; q++) {
            int id = tid + q * 256;
            ((float4*)Ws)[id] = ((const float4*)&W[kt * 16 * DD])[id];
        }
        __syncthreads();

#pragma unroll
        for (int k = 0; k < 16; k++) {
            float4 a0 = *(float4*)&As[k][ty * 8];
            float4 a1 = *(float4*)&As[k][ty * 8 + 4];
            ulonglong2 w0 = *(ulonglong2*)&Ws[k][tx * 8];
            ulonglong2 w1 = *(ulonglong2*)&Ws[k][tx * 8 + 4];
            unsigned long long wp[4] = {w0.x, w0.y, w1.x, w1.y};
            float av[8] = {a0.x, a0.y, a0.z, a0.w, a1.x, a1.y, a1.z, a1.w};
#pragma unroll
            for (int i = 0; i < 8; i++) {
                unsigned long long ap;
                asm("mov.b64 %0, {%1, %1};" : "=l"(ap) : "r"(__float_as_uint(av[i])));
#pragma unroll
                for (int j = 0; j < 4; j++) {
                    asm("fma.rn.f32x2 %0, %1, %2, %0;"
                        : "+l"(acc[i][j]) : "l"(ap), "l"(wp[j]));
                }
            }
        }
        __syncthreads();
    }

    // store 8x8 per thread
#pragma unroll
    for (int i = 0; i < 8; i++) {
        int grow = row0 + ty * 8 + i;
        if (grow < M) {
            float o[8];
#pragma unroll
            for (int j = 0; j < 4; j++) {
                unsigned int lo, hi;
                asm("mov.b64 {%0, %1}, %2;" : "=r"(lo), "=r"(hi) : "l"(acc[i][j]));
                o[2 * j] = __uint_as_float(lo);
                o[2 * j + 1] = __uint_as_float(hi);
            }
            *(float4*)&C[(size_t)grow * DD + tx * 8] = make_float4(o[0], o[1], o[2], o[3]);
            *(float4*)&C[(size_t)grow * DD + tx * 8 + 4] = make_float4(o[4], o[5], o[6], o[7]);
        }
    }
}

// ================= self-loop + bias init: agg[i] = b + tmp[i]*dinv[i]^2 =================
__global__ void k_selfinit(const float* __restrict__ b) {
    int t = blockIdx.x * blockDim.x + threadIdx.x;   // float4 index
    if (t < NN * 32) {
        int node = t >> 5;
        int c4 = t & 31;
        float di = g_dinv[node];
        float n2 = di * di;
        float4 v = ((const float4*)g_tmp)[t];
        float4 bb = ((const float4*)b)[c4];
        v.x = fmaf(v.x, n2, bb.x); v.y = fmaf(v.y, n2, bb.y);
        v.z = fmaf(v.z, n2, bb.z); v.w = fmaf(v.w, n2, bb.w);
        ((float4*)g_h)[t] = v;
    }
}

// ================= edge scatter: agg[dst] += tmp[src] * dinv[src]*dinv[dst] =================
// one warp per edge; lane handles one float4 (128 floats = 32 lanes x 4)
__global__ void k_edge(const int* __restrict__ ei) {
    int t = blockIdx.x * blockDim.x + threadIdx.x;
    int e = t >> 5;
    int lane = t & 31;
    if (e < EE) {
        int s = ei[e];
        int d = ei[EE + e];
        float nm = g_dinv[s] * g_dinv[d];
        float4 v = ((const float4*)g_tmp)[s * 32 + lane];
        float* p = &g_h[(size_t)d * DD + lane * 4];
        asm volatile("red.global.add.v4.f32 [%0], {%1, %2, %3, %4};"
                     :: "l"(p), "f"(v.x * nm), "f"(v.y * nm), "f"(v.z * nm), "f"(v.w * nm)
                     : "memory");
    }
}

// ================= global mean pool =================
__global__ void k_pool_zero(float* __restrict__ out) {
    int i = blockIdx.x * blockDim.x + threadIdx.x;
    if (i < NG * DD) out[i] = 0.f;
    if (i < NG) g_cnt[i] = 0.f;
}

__global__ void k_pool(const int* __restrict__ batch, float* __restrict__ out) {
    int t = blockIdx.x * blockDim.x + threadIdx.x;
    int node = t >> 5;
    int lane = t & 31;
    if (node < NN) {
        int g = batch[node];
        float4 v = ((const float4*)g_h)[node * 32 + lane];
        // final relu folded here
        v.x = fmaxf(v.x, 0.f); v.y = fmaxf(v.y, 0.f);
        v.z = fmaxf(v.z, 0.f); v.w = fmaxf(v.w, 0.f);
        float* p = &out[g * DD + lane * 4];
        asm volatile("red.global.add.v4.f32 [%0], {%1, %2, %3, %4};"
                     :: "l"(p), "f"(v.x), "f"(v.y), "f"(v.z), "f"(v.w)
                     : "memory");
        if (lane == 0) atomicAdd(&g_cnt[g], 1.0f);
    }
}

__global__ void k_pool_div(float* __restrict__ out) {
    int i = blockIdx.x * blockDim.x + threadIdx.x;
    if (i < NG * DD) out[i] /= fmaxf(g_cnt[i >> 7], 1.0f);
}

// ================= launch =================
extern "C" void kernel_launch(void* const* d_in, const int* in_sizes, int n_in,
                              void* d_out, int out_size) {
    const float* x = (const float*)d_in[0];
    const int* ei = (const int*)d_in[1];      // int32: JAX x64 disabled downgrades int64
    const int* batch = (const int*)d_in[2];   // int32
    const float* W0 = (const float*)d_in[3];
    const float* b0 = (const float*)d_in[4];
    const float* W1 = (const float*)d_in[5];
    const float* b1 = (const float*)d_in[6];
    const float* W2 = (const float*)d_in[7];
    const float* b2 = (const float*)d_in[8];
    float* out = (float*)d_out;

    float* tmp; cudaGetSymbolAddress((void**)&tmp, g_tmp);
    float* h;   cudaGetSymbolAddress((void**)&h, g_h);

    const int TB = 256;
    // degrees
    k_deg_init<<<(NN + TB - 1) / TB, TB>>>();
    k_deg_count<<<(EE + TB - 1) / TB, TB>>>(ei);
    k_deg_rsqrt<<<(NN + TB - 1) / TB, TB>>>();

    int gemm_blocks = (NN + 127) / 128;
    int elem4_blocks = (NN * 32 + TB - 1) / TB;
    int edge_blocks = (EE * 32 + TB - 1) / TB;

    // layer 0
    k_gemm<<<gemm_blocks, TB>>>(x, W0, tmp, NN, 0);
    k_selfinit<<<elem4_blocks, TB>>>(b0);
    k_edge<<<edge_blocks, TB>>>(ei);
    // layer 1 (relu folded into A-load)
    k_gemm<<<gemm_blocks, TB>>>(h, W1, tmp, NN, 1);
    k_selfinit<<<elem4_blocks, TB>>>(b1);
    k_edge<<<edge_blocks, TB>>>(ei);
    // layer 2
    k_gemm<<<gemm_blocks, TB>>>(h, W2, tmp, NN, 1);
    k_selfinit<<<elem4_blocks, TB>>>(b2);
    k_edge<<<edge_blocks, TB>>>(ei);

    // pool
    k_pool_zero<<<(NG * DD + TB - 1) / TB, TB>>>(out);
    k_pool<<<elem4_blocks, TB>>>(batch, out);
    k_pool_div<<<(NG * DD + TB - 1) / TB, TB>>>(out);
}

// round 4
// speedup vs baseline: 1.2114x; 1.2114x over previous
#include <cuda_runtime.h>
#include <cuda_bf16.h>

#define NN 50000
#define EE 800000
#define DD 128
#define NG 64

// -------- scratch (device globals: no allocation allowed) --------
__device__ __align__(16) float g_tmp[NN * DD];   // h @ W result
__device__ __align__(16) float g_h[NN * DD];     // aggregated layer output
__device__ __align__(16) float g_dinv[NN];       // rsqrt(degree)
__device__ __align__(16) float g_cnt[NG];        // pool counts
__device__ __align__(16) int   g_degi[NN];       // int in-degree (no self loop)
__device__ __align__(16) int   g_rowptr[NN + 1]; // CSR row pointers (by dst)
__device__ __align__(16) int   g_cursor[NN];     // scatter cursors
__device__ __align__(16) int   g_csr_src[EE];    // CSR column = src node
__device__ __align__(16) float g_csr_nrm[EE];    // precomputed edge norm

// ================= degree count (int) =================
__global__ void k_zero() {
    int i = blockIdx.x * blockDim.x + threadIdx.x;
    if (i < NN) g_degi[i] = 0;
    if (i < NG) g_cnt[i] = 0.f;
}

__global__ void k_deg_count(const int* __restrict__ ei) {
    int e = blockIdx.x * blockDim.x + threadIdx.x;
    if (e < EE) atomicAdd(&g_degi[ei[EE + e]], 1);
}

// ================= single-block scan: rowptr, cursor, dinv =================
__global__ void k_scan() {
    __shared__ int sh[1024];
    int tid = threadIdx.x;
    int run = 0;
    for (int base = 0; base < NN; base += 1024) {
        int i = base + tid;
        int v = (i < NN) ? g_degi[i] : 0;
        sh[tid] = v;
        __syncthreads();
        for (int off = 1; off < 1024; off <<= 1) {
            int y = (tid >= off) ? sh[tid - off] : 0;
            __syncthreads();
            sh[tid] += y;
            __syncthreads();
        }
        if (i < NN) {
            int excl = run + sh[tid] - v;
            g_rowptr[i] = excl;
            g_cursor[i] = excl;
            g_dinv[i] = rsqrtf((float)(v + 1));   // +1 self loop
        }
        int total = sh[1023];
        __syncthreads();
        run += total;
    }
    if (tid == 0) g_rowptr[NN] = run;
}

// ================= CSR fill with precomputed norms =================
__global__ void k_csr_fill(const int* __restrict__ ei) {
    int e = blockIdx.x * blockDim.x + threadIdx.x;
    if (e < EE) {
        int s = ei[e];
        int d = ei[EE + e];
        int pos = atomicAdd(&g_cursor[d], 1);
        g_csr_src[pos] = s;
        g_csr_nrm[pos] = g_dinv[s] * g_dinv[d];
    }
}

// ================= pool counts =================
__global__ void k_cnt(const int* __restrict__ batch) {
    int i = blockIdx.x * blockDim.x + threadIdx.x;
    if (i < NN) atomicAdd(&g_cnt[batch[i]], 1.0f);
}

// ================= GEMM: C[M,128] = reluOpt(A)[M,128] @ W[128,128] =================
__global__ __launch_bounds__(256, 2)
void k_gemm(const float* __restrict__ A, const float* __restrict__ W,
            float* __restrict__ C, int M, int relu_in) {
    __shared__ float As[16][128];
    __shared__ float Ws[16][128];

    int tid = threadIdx.x;
    int tx = tid & 15;
    int ty = tid >> 4;
    int row0 = blockIdx.x * 128;

    unsigned long long acc[8][4];
#pragma unroll
    for (int i = 0; i < 8; i++)
#pragma unroll
        for (int j = 0; j < 4; j++) acc[i][j] = 0ull;

    for (int kt = 0; kt < 8; kt++) {
#pragma unroll
        for (int q = 0; q < 2; q++) {
            int id = tid + q * 256;
            int r = id >> 2;
            int kc = (id & 3) * 4;
            int grow = row0 + r;
            float4 v = make_float4(0.f, 0.f, 0.f, 0.f);
            if (grow < M) v = *(const float4*)&A[(size_t)grow * DD + kt * 16 + kc];
            if (relu_in) {
                v.x = fmaxf(v.x, 0.f); v.y = fmaxf(v.y, 0.f);
                v.z = fmaxf(v.z, 0.f); v.w = fmaxf(v.w, 0.f);
            }
            As[kc + 0][r] = v.x; As[kc + 1][r] = v.y;
            As[kc + 2][r] = v.z; As[kc + 3][r] = v.w;
        }
#pragma unroll
        for (int q = 0; q < 2; q++) {
            int id = tid + q * 256;
            ((float4*)Ws)[id] = ((const float4*)&W[kt * 16 * DD])[id];
        }
        __syncthreads();

#pragma unroll
        for (int k = 0; k < 16; k++) {
            float4 a0 = *(float4*)&As[k][ty * 8];
            float4 a1 = *(float4*)&As[k][ty * 8 + 4];
            ulonglong2 w0 = *(ulonglong2*)&Ws[k][tx * 8];
            ulonglong2 w1 = *(ulonglong2*)&Ws[k][tx * 8 + 4];
            unsigned long long wp[4] = {w0.x, w0.y, w1.x, w1.y};
            float av[8] = {a0.x, a0.y, a0.z, a0.w, a1.x, a1.y, a1.z, a1.w};
#pragma unroll
            for (int i = 0; i < 8; i++) {
                unsigned long long ap;
                asm("mov.b64 %0, {%1, %1};" : "=l"(ap) : "r"(__float_as_uint(av[i])));
#pragma unroll
                for (int j = 0; j < 4; j++) {
                    asm("fma.rn.f32x2 %0, %1, %2, %0;"
                        : "+l"(acc[i][j]) : "l"(ap), "l"(wp[j]));
                }
            }
        }
        __syncthreads();
    }

#pragma unroll
    for (int i = 0; i < 8; i++) {
        int grow = row0 + ty * 8 + i;
        if (grow < M) {
            float o[8];
#pragma unroll
            for (int j = 0; j < 4; j++) {
                unsigned int lo, hi;
                asm("mov.b64 {%0, %1}, %2;" : "=r"(lo), "=r"(hi) : "l"(acc[i][j]));
                o[2 * j] = __uint_as_float(lo);
                o[2 * j + 1] = __uint_as_float(hi);
            }
            *(float4*)&C[(size_t)grow * DD + tx * 8] = make_float4(o[0], o[1], o[2], o[3]);
            *(float4*)&C[(size_t)grow * DD + tx * 8 + 4] = make_float4(o[4], o[5], o[6], o[7]);
        }
    }
}

// ================= gather aggregation: one warp per dst node =================
// acc = b + tmp[d]*dinv[d]^2 + sum_in_edges tmp[s]*nrm ; FINAL: relu + pool-red
template <int FINAL>
__global__ void k_agg(const float* __restrict__ b,
                      const int* __restrict__ batch,
                      float* __restrict__ out) {
    int warp = (blockIdx.x * blockDim.x + threadIdx.x) >> 5;
    int lane = threadIdx.x & 31;
    if (warp >= NN) return;
    int d = warp;

    float di = g_dinv[d];
    float n2 = di * di;
    float4 bb = ((const float4*)b)[lane];
    float4 v = ((const float4*)g_tmp)[d * 32 + lane];
    float4 acc;
    acc.x = fmaf(v.x, n2, bb.x); acc.y = fmaf(v.y, n2, bb.y);
    acc.z = fmaf(v.z, n2, bb.z); acc.w = fmaf(v.w, n2, bb.w);

    int idx = g_rowptr[d];
    int end = g_rowptr[d + 1];
    // unroll by 2 for memory-level parallelism
    for (; idx + 1 < end; idx += 2) {
        int s0 = g_csr_src[idx];
        int s1 = g_csr_src[idx + 1];
        float n0 = g_csr_nrm[idx];
        float n1 = g_csr_nrm[idx + 1];
        float4 u0 = ((const float4*)g_tmp)[s0 * 32 + lane];
        float4 u1 = ((const float4*)g_tmp)[s1 * 32 + lane];
        acc.x = fmaf(u0.x, n0, acc.x); acc.y = fmaf(u0.y, n0, acc.y);
        acc.z = fmaf(u0.z, n0, acc.z); acc.w = fmaf(u0.w, n0, acc.w);
        acc.x = fmaf(u1.x, n1, acc.x); acc.y = fmaf(u1.y, n1, acc.y);
        acc.z = fmaf(u1.z, n1, acc.z); acc.w = fmaf(u1.w, n1, acc.w);
    }
    if (idx < end) {
        int s = g_csr_src[idx];
        float nm = g_csr_nrm[idx];
        float4 u = ((const float4*)g_tmp)[s * 32 + lane];
        acc.x = fmaf(u.x, nm, acc.x); acc.y = fmaf(u.y, nm, acc.y);
        acc.z = fmaf(u.z, nm, acc.z); acc.w = fmaf(u.w, nm, acc.w);
    }

    if (FINAL) {
        acc.x = fmaxf(acc.x, 0.f); acc.y = fmaxf(acc.y, 0.f);
        acc.z = fmaxf(acc.z, 0.f); acc.w = fmaxf(acc.w, 0.f);
        int g = batch[d];
        float* p = &out[g * DD + lane * 4];
        asm volatile("red.global.add.v4.f32 [%0], {%1, %2, %3, %4};"
                     :: "l"(p), "f"(acc.x), "f"(acc.y), "f"(acc.z), "f"(acc.w)
                     : "memory");
    } else {
        ((float4*)g_h)[d * 32 + lane] = acc;
    }
}

// ================= output zero + final divide =================
__global__ void k_out_zero(float* __restrict__ out) {
    int i = blockIdx.x * blockDim.x + threadIdx.x;
    if (i < NG * DD) out[i] = 0.f;
}

__global__ void k_pool_div(float* __restrict__ out) {
    int i = blockIdx.x * blockDim.x + threadIdx.x;
    if (i < NG * DD) out[i] /= fmaxf(g_cnt[i >> 7], 1.0f);
}

// ================= launch =================
extern "C" void kernel_launch(void* const* d_in, const int* in_sizes, int n_in,
                              void* d_out, int out_size) {
    const float* x = (const float*)d_in[0];
    const int* ei = (const int*)d_in[1];      // int32 (JAX x64 disabled)
    const int* batch = (const int*)d_in[2];
    const float* W0 = (const float*)d_in[3];
    const float* b0 = (const float*)d_in[4];
    const float* W1 = (const float*)d_in[5];
    const float* b1 = (const float*)d_in[6];
    const float* W2 = (const float*)d_in[7];
    const float* b2 = (const float*)d_in[8];
    float* out = (float*)d_out;

    float* tmp; cudaGetSymbolAddress((void**)&tmp, g_tmp);
    float* h;   cudaGetSymbolAddress((void**)&h, g_h);

    const int TB = 256;
    int nodeB = (NN + TB - 1) / TB;
    int edgeB = (EE + TB - 1) / TB;
    int gemmB = (NN + 127) / 128;
    int aggB = (NN * 32 + TB - 1) / TB;   // warp per node

    // ---- graph preprocessing (once) ----
    k_zero<<<nodeB, TB>>>();
    k_deg_count<<<edgeB, TB>>>(ei);
    k_scan<<<1, 1024>>>();
    k_csr_fill<<<edgeB, TB>>>(ei);
    k_cnt<<<nodeB, TB>>>(batch);
    k_out_zero<<<(NG * DD + TB - 1) / TB, TB>>>(out);

    // ---- layer 0 ----
    k_gemm<<<gemmB, TB>>>(x, W0, tmp, NN, 0);
    k_agg<0><<<aggB, TB>>>(b0, batch, out);
    // ---- layer 1 ----
    k_gemm<<<gemmB, TB>>>(h, W1, tmp, NN, 1);
    k_agg<0><<<aggB, TB>>>(b1, batch, out);
    // ---- layer 2 (fused relu + pool) ----
    k_gemm<<<gemmB, TB>>>(h, W2, tmp, NN, 1);
    k_agg<1><<<aggB, TB>>>(b2, batch, out);

    k_pool_div<<<(NG * DD + TB - 1) / TB, TB>>>(out);
}

// round 6
// speedup vs baseline: 1.4204x; 1.1726x over previous
#include <cuda_runtime.h>
#include <cuda_bf16.h>
#include <cstdint>

#define NN 50000
#define EE 800000
#define DD 128
#define NG 64

// -------- scratch (device globals: no allocation allowed) --------
__device__ __align__(16) float g_tmp[NN * DD];   // h @ W result
__device__ __align__(16) float g_h[NN * DD];     // aggregated layer output
__device__ __align__(16) float g_dinv[NN];       // rsqrt(degree)
__device__ __align__(16) float g_cnt[NG];        // pool counts
__device__ __align__(16) int   g_degi[NN];       // int in-degree (no self loop)
__device__ __align__(16) int   g_rowptr[NN + 1]; // CSR row pointers (by dst)
__device__ __align__(16) int   g_cursor[NN];     // scatter cursors
__device__ __align__(16) int   g_csr_src[EE];    // CSR column = src node
__device__ __align__(16) float g_csr_nrm[EE];    // precomputed edge norm

// ================= prep =================
__global__ void k_zero(float* __restrict__ out) {
    int i = blockIdx.x * blockDim.x + threadIdx.x;
    if (i < NN) g_degi[i] = 0;
    if (i < NG) g_cnt[i] = 0.f;
    if (i < NG * DD) out[i] = 0.f;
}

__global__ void k_deg_count(const int* __restrict__ ei) {
    int e = blockIdx.x * blockDim.x + threadIdx.x;
    if (e < EE) atomicAdd(&g_degi[ei[EE + e]], 1);
}

// warp-shuffle scan, 1024 threads, 3 barriers per 1024-chunk
__global__ void k_scan() {
    __shared__ int wsum[32];
    int tid = threadIdx.x, lane = tid & 31, wd = tid >> 5;
    int run = 0;
    for (int base = 0; base < NN; base += 1024) {
        int i = base + tid;
        int v = (i < NN) ? g_degi[i] : 0;
        int x = v;
#pragma unroll
        for (int o = 1; o < 32; o <<= 1) {
            int y = __shfl_up_sync(0xffffffffu, x, o);
            if (lane >= o) x += y;
        }
        if (lane == 31) wsum[wd] = x;
        __syncthreads();
        if (wd == 0) {
            int s = wsum[lane];
#pragma unroll
            for (int o = 1; o < 32; o <<= 1) {
                int y = __shfl_up_sync(0xffffffffu, s, o);
                if (lane >= o) s += y;
            }
            wsum[lane] = s;
        }
        __syncthreads();
        int excl = run + (wd ? wsum[wd - 1] : 0) + x - v;
        if (i < NN) {
            g_rowptr[i] = excl;
            g_cursor[i] = excl;
            g_dinv[i] = rsqrtf((float)(v + 1));
        }
        int tot = wsum[31];
        __syncthreads();
        run += tot;
    }
    if (tid == 0) g_rowptr[NN] = run;
}

// CSR fill + pool-count fused (first NN threads also count batch)
__global__ void k_csr_fill(const int* __restrict__ ei, const int* __restrict__ batch) {
    int e = blockIdx.x * blockDim.x + threadIdx.x;
    if (e < NN) atomicAdd(&g_cnt[batch[e]], 1.0f);
    if (e < EE) {
        int s = ei[e];
        int d = ei[EE + e];
        int pos = atomicAdd(&g_cursor[d], 1);
        g_csr_src[pos] = s;
        g_csr_nrm[pos] = g_dinv[s] * g_dinv[d];
    }
}

// ================= GEMM: C[M,128] = reluOpt(A)[M,128] @ W[128,128] =================
// 64x128 tile, 128 threads, 8x8 micro-tile, double-buffered smem,
// packed fp32 via fma.rn.f32x2. 4 CTAs/SM.
__global__ __launch_bounds__(128, 4)
void k_gemm(const float* __restrict__ A, const float* __restrict__ W,
            float* __restrict__ C, int M, int relu_in) {
    __shared__ float As[2][16][68];    // [buf][k][row], pad 68 (16B-aligned rows, 2-way sts)
    __shared__ float Ws[2][16][128];   // [buf][k][col]

    int tid = threadIdx.x;
    int tx = tid & 15;        // col group (8 cols)
    int ty = tid >> 4;        // row group (8 rows), 0..7
    int row0 = blockIdx.x * 64;

    unsigned long long acc[8][4];
#pragma unroll
    for (int i = 0; i < 8; i++)
#pragma unroll
        for (int j = 0; j < 4; j++) acc[i][j] = 0ull;

    float4 aR[2];   // A stage: 2 float4/thread (64*16 floats / 128 thr)
    float4 wR[4];   // W stage: 4 float4/thread (16*128 floats / 128 thr)

    // ---- register loads for k-tile kt ----
    auto loadT = [&](int kt) {
#pragma unroll
        for (int q = 0; q < 2; q++) {
            int id = tid + q * 128;          // 0..255 float4 slots of A tile
            int r = id >> 2;
            int kc = (id & 3) * 4;
            int grow = row0 + r;
            float4 v = make_float4(0.f, 0.f, 0.f, 0.f);
            if (grow < M) v = *(const float4*)&A[(size_t)grow * DD + kt * 16 + kc];
            if (relu_in) {
                v.x = fmaxf(v.x, 0.f); v.y = fmaxf(v.y, 0.f);
                v.z = fmaxf(v.z, 0.f); v.w = fmaxf(v.w, 0.f);
            }
            aR[q] = v;
        }
#pragma unroll
        for (int q = 0; q < 4; q++) {
            int id = tid + q * 128;          // 0..511 float4 slots of W tile
            wR[q] = ((const float4*)&W[kt * 16 * DD])[id];
        }
    };
    auto stsT = [&](int b) {
#pragma unroll
        for (int q = 0; q < 2; q++) {
            int id = tid + q * 128;
            int r = id >> 2;
            int kc = (id & 3) * 4;
            As[b][kc + 0][r] = aR[q].x;
            As[b][kc + 1][r] = aR[q].y;
            As[b][kc + 2][r] = aR[q].z;
            As[b][kc + 3][r] = aR[q].w;
        }
#pragma unroll
        for (int q = 0; q < 4; q++) {
            int id = tid + q * 128;
            ((float4*)Ws[b])[id] = wR[q];
        }
    };

    loadT(0);
    stsT(0);
    __syncthreads();

    for (int kt = 0; kt < 8; kt++) {
        if (kt < 7) loadT(kt + 1);
        int b = kt & 1;
#pragma unroll
        for (int k = 0; k < 16; k++) {
            float4 a0 = *(float4*)&As[b][k][ty * 8];
            float4 a1 = *(float4*)&As[b][k][ty * 8 + 4];
            ulonglong2 w0 = *(ulonglong2*)&Ws[b][k][tx * 8];
            ulonglong2 w1 = *(ulonglong2*)&Ws[b][k][tx * 8 + 4];
            unsigned long long wp[4] = {w0.x, w0.y, w1.x, w1.y};
            float av[8] = {a0.x, a0.y, a0.z, a0.w, a1.x, a1.y, a1.z, a1.w};
#pragma unroll
            for (int i = 0; i < 8; i++) {
                unsigned long long ap;
                asm("mov.b64 %0, {%1, %1};" : "=l"(ap) : "r"(__float_as_uint(av[i])));
#pragma unroll
                for (int j = 0; j < 4; j++) {
                    asm("fma.rn.f32x2 %0, %1, %2, %0;"
                        : "+l"(acc[i][j]) : "l"(ap), "l"(wp[j]));
                }
            }
        }
        if (kt < 7) {
            stsT((kt + 1) & 1);
            __syncthreads();
        }
    }

#pragma unroll
    for (int i = 0; i < 8; i++) {
        int grow = row0 + ty * 8 + i;
        if (grow < M) {
            float o[8];
#pragma unroll
            for (int j = 0; j < 4; j++) {
                unsigned int lo, hi;
                asm("mov.b64 {%0, %1}, %2;" : "=r"(lo), "=r"(hi) : "l"(acc[i][j]));
                o[2 * j] = __uint_as_float(lo);
                o[2 * j + 1] = __uint_as_float(hi);
            }
            *(float4*)&C[(size_t)grow * DD + tx * 8] = make_float4(o[0], o[1], o[2], o[3]);
            *(float4*)&C[(size_t)grow * DD + tx * 8 + 4] = make_float4(o[4], o[5], o[6], o[7]);
        }
    }
}

// ================= gather aggregation: one warp per dst node =================
template <int FINAL>
__global__ void k_agg(const float* __restrict__ b,
                      const int* __restrict__ batch,
                      float* __restrict__ out) {
    int warp = (blockIdx.x * blockDim.x + threadIdx.x) >> 5;
    int lane = threadIdx.x & 31;
    if (warp >= NN) return;
    int d = warp;

    float di = g_dinv[d];
    float n2 = di * di;
    float4 bb = ((const float4*)b)[lane];
    float4 v = ((const float4*)g_tmp)[d * 32 + lane];
    float4 acc;
    acc.x = fmaf(v.x, n2, bb.x); acc.y = fmaf(v.y, n2, bb.y);
    acc.z = fmaf(v.z, n2, bb.z); acc.w = fmaf(v.w, n2, bb.w);

    int idx = g_rowptr[d];
    int end = g_rowptr[d + 1];
    for (; idx + 1 < end; idx += 2) {
        int s0 = g_csr_src[idx];
        int s1 = g_csr_src[idx + 1];
        float n0 = g_csr_nrm[idx];
        float n1 = g_csr_nrm[idx + 1];
        float4 u0 = ((const float4*)g_tmp)[s0 * 32 + lane];
        float4 u1 = ((const float4*)g_tmp)[s1 * 32 + lane];
        acc.x = fmaf(u0.x, n0, acc.x); acc.y = fmaf(u0.y, n0, acc.y);
        acc.z = fmaf(u0.z, n0, acc.z); acc.w = fmaf(u0.w, n0, acc.w);
        acc.x = fmaf(u1.x, n1, acc.x); acc.y = fmaf(u1.y, n1, acc.y);
        acc.z = fmaf(u1.z, n1, acc.z); acc.w = fmaf(u1.w, n1, acc.w);
    }
    if (idx < end) {
        int s = g_csr_src[idx];
        float nm = g_csr_nrm[idx];
        float4 u = ((const float4*)g_tmp)[s * 32 + lane];
        acc.x = fmaf(u.x, nm, acc.x); acc.y = fmaf(u.y, nm, acc.y);
        acc.z = fmaf(u.z, nm, acc.z); acc.w = fmaf(u.w, nm, acc.w);
    }

    if (FINAL) {
        acc.x = fmaxf(acc.x, 0.f); acc.y = fmaxf(acc.y, 0.f);
        acc.z = fmaxf(acc.z, 0.f); acc.w = fmaxf(acc.w, 0.f);
        int g = batch[d];
        float* p = &out[g * DD + lane * 4];
        asm volatile("red.global.add.v4.f32 [%0], {%1, %2, %3, %4};"
                     :: "l"(p), "f"(acc.x), "f"(acc.y), "f"(acc.z), "f"(acc.w)
                     : "memory");
    } else {
        ((float4*)g_h)[d * 32 + lane] = acc;
    }
}

__global__ void k_pool_div(float* __restrict__ out) {
    int i = blockIdx.x * blockDim.x + threadIdx.x;
    if (i < NG * DD) out[i] /= fmaxf(g_cnt[i >> 7], 1.0f);
}

// ================= launch =================
extern "C" void kernel_launch(void* const* d_in, const int* in_sizes, int n_in,
                              void* d_out, int out_size) {
    const float* x = (const float*)d_in[0];
    const int* ei = (const int*)d_in[1];      // int32 (JAX x64 disabled)
    const int* batch = (const int*)d_in[2];
    const float* W0 = (const float*)d_in[3];
    const float* b0 = (const float*)d_in[4];
    const float* W1 = (const float*)d_in[5];
    const float* b1 = (const float*)d_in[6];
    const float* W2 = (const float*)d_in[7];
    const float* b2 = (const float*)d_in[8];
    float* out = (float*)d_out;

    float* tmp; cudaGetSymbolAddress((void**)&tmp, g_tmp);
    float* h;   cudaGetSymbolAddress((void**)&h, g_h);

    const int TB = 256;
    int nodeB = (NN + TB - 1) / TB;
    int edgeB = (EE + TB - 1) / TB;
    int gemmB = (NN + 63) / 64;
    int aggB = (NN * 32 + TB - 1) / TB;

    // ---- graph preprocessing (once) ----
    k_zero<<<nodeB, TB>>>(out);
    k_deg_count<<<edgeB, TB>>>(ei);
    k_scan<<<1, 1024>>>();
    k_csr_fill<<<edgeB, TB>>>(ei, batch);

    // ---- layer 0 ----
    k_gemm<<<gemmB, 128>>>(x, W0, tmp, NN, 0);
    k_agg<0><<<aggB, TB>>>(b0, batch, out);
    // ---- layer 1 ----
    k_gemm<<<gemmB, 128>>>(h, W1, tmp, NN, 1);
    k_agg<0><<<aggB, TB>>>(b1, batch, out);
    // ---- layer 2 (fused relu + pool) ----
    k_gemm<<<gemmB, 128>>>(h, W2, tmp, NN, 1);
    k_agg<1><<<aggB, TB>>>(b2, batch, out);

    k_pool_div<<<(NG * DD + TB - 1) / TB, TB>>>(out);
}

// round 7
// speedup vs baseline: 1.6351x; 1.1511x over previous
#include <cuda_runtime.h>
#include <cuda_bf16.h>
#include <cstdint>

#define NN 50000
#define EE 800000
#define DD 128
#define NG 64
#define SCAN_CHUNK 1024
#define NCHUNK ((NN + SCAN_CHUNK - 1) / SCAN_CHUNK)   // 49

// -------- scratch (device globals: no allocation allowed) --------
__device__ __align__(16) float g_tmp[NN * DD];   // h @ W result
__device__ __align__(16) float g_h[NN * DD];     // aggregated layer output
__device__ __align__(16) float g_dinv[NN];       // rsqrt(degree)
__device__ __align__(16) float g_cnt[NG];        // pool counts
__device__ __align__(16) int   g_degi[NN];       // int in-degree (no self loop)
__device__ __align__(16) int   g_rowptr[NN + 1]; // CSR row pointers (by dst)
__device__ __align__(16) int   g_cursor[NN];     // scatter cursors
__device__ __align__(16) int2  g_csr[EE];        // {src, norm-as-int}
__device__ __align__(16) int   g_bsum[NCHUNK];   // scan block sums (exclusive after phase2)

// ================= prep =================
__global__ void k_zero(float* __restrict__ out) {
    int i = blockIdx.x * blockDim.x + threadIdx.x;
    if (i < NN) g_degi[i] = 0;
    if (i < NG * DD) out[i] = 0.f;
}

__global__ void k_deg_count(const int* __restrict__ ei) {
    int e = blockIdx.x * blockDim.x + threadIdx.x;
    if (e < EE) atomicAdd(&g_degi[ei[EE + e]], 1);
}

// ---- scan phase 1: per-chunk exclusive scan into rowptr, chunk total to g_bsum ----
__global__ void k_scan1() {
    __shared__ int wsum[32];
    int tid = threadIdx.x, lane = tid & 31, wd = tid >> 5;
    int i = blockIdx.x * SCAN_CHUNK + tid;
    int v = (i < NN) ? g_degi[i] : 0;
    int x = v;
#pragma unroll
    for (int o = 1; o < 32; o <<= 1) {
        int y = __shfl_up_sync(0xffffffffu, x, o);
        if (lane >= o) x += y;
    }
    if (lane == 31) wsum[wd] = x;
    __syncthreads();
    if (wd == 0) {
        int s = wsum[lane];
#pragma unroll
        for (int o = 1; o < 32; o <<= 1) {
            int y = __shfl_up_sync(0xffffffffu, s, o);
            if (lane >= o) s += y;
        }
        wsum[lane] = s;
    }
    __syncthreads();
    int excl = (wd ? wsum[wd - 1] : 0) + x - v;
    if (i < NN) g_rowptr[i] = excl;
    if (tid == SCAN_CHUNK - 1) g_bsum[blockIdx.x] = wsum[31];
}

// ---- scan phase 2: exclusive scan of 49 block sums (single warp pair) ----
__global__ void k_scan2() {
    __shared__ int sh[64];
    int tid = threadIdx.x;
    sh[tid] = (tid < NCHUNK) ? g_bsum[tid] : 0;
    __syncthreads();
    if (tid == 0) {
        int run = 0;
        for (int j = 0; j < NCHUNK; j++) {
            int t = sh[j];
            sh[j] = run;
            run += t;
        }
    }
    __syncthreads();
    if (tid < NCHUNK) g_bsum[tid] = sh[tid];
}

// ---- scan phase 3: add chunk offsets, write cursor + dinv ----
__global__ void k_scan3() {
    int i = blockIdx.x * blockDim.x + threadIdx.x;
    if (i < NN) {
        int rp = g_rowptr[i] + g_bsum[i / SCAN_CHUNK];
        g_rowptr[i] = rp;
        g_cursor[i] = rp;
        g_dinv[i] = rsqrtf((float)(g_degi[i] + 1));
    }
    if (i == 0) g_rowptr[NN] = EE;
}

// ---- CSR fill: one 8B write per edge ----
__global__ void k_csr_fill(const int* __restrict__ ei) {
    int e = blockIdx.x * blockDim.x + threadIdx.x;
    if (e < EE) {
        int s = ei[e];
        int d = ei[EE + e];
        int pos = atomicAdd(&g_cursor[d], 1);
        float nm = g_dinv[s] * g_dinv[d];
        g_csr[pos] = make_int2(s, __float_as_int(nm));
    }
}

// ---- pool counts from sorted batch: binary search bounds, no atomics ----
__global__ void k_cnt(const int* __restrict__ batch) {
    int g = threadIdx.x;
    if (g < NG) {
        int lo = 0, hi = NN;
        while (lo < hi) { int m = (lo + hi) >> 1; if (batch[m] < g) lo = m + 1; else hi = m; }
        int start = lo;
        lo = 0; hi = NN;
        while (lo < hi) { int m = (lo + hi) >> 1; if (batch[m] <= g) lo = m + 1; else hi = m; }
        g_cnt[g] = (float)(lo - start);
    }
}

// ================= GEMM: C[M,128] = reluOpt(A)[M,128] @ W[128,128] =================
// 64x128 tile, 128 threads, 8x8 micro-tile, double-buffered smem,
// packed fp32 via fma.rn.f32x2. 4 CTAs/SM.
__global__ __launch_bounds__(128, 4)
void k_gemm(const float* __restrict__ A, const float* __restrict__ W,
            float* __restrict__ C, int M, int relu_in) {
    __shared__ float As[2][16][68];
    __shared__ float Ws[2][16][128];

    int tid = threadIdx.x;
    int tx = tid & 15;
    int ty = tid >> 4;
    int row0 = blockIdx.x * 64;

    unsigned long long acc[8][4];
#pragma unroll
    for (int i = 0; i < 8; i++)
#pragma unroll
        for (int j = 0; j < 4; j++) acc[i][j] = 0ull;

    float4 aR[2];
    float4 wR[4];

    auto loadT = [&](int kt) {
#pragma unroll
        for (int q = 0; q < 2; q++) {
            int id = tid + q * 128;
            int r = id >> 2;
            int kc = (id & 3) * 4;
            int grow = row0 + r;
            float4 v = make_float4(0.f, 0.f, 0.f, 0.f);
            if (grow < M) v = *(const float4*)&A[(size_t)grow * DD + kt * 16 + kc];
            if (relu_in) {
                v.x = fmaxf(v.x, 0.f); v.y = fmaxf(v.y, 0.f);
                v.z = fmaxf(v.z, 0.f); v.w = fmaxf(v.w, 0.f);
            }
            aR[q] = v;
        }
#pragma unroll
        for (int q = 0; q < 4; q++) {
            int id = tid + q * 128;
            wR[q] = ((const float4*)&W[kt * 16 * DD])[id];
        }
    };
    auto stsT = [&](int b) {
#pragma unroll
        for (int q = 0; q < 2; q++) {
            int id = tid + q * 128;
            int r = id >> 2;
            int kc = (id & 3) * 4;
            As[b][kc + 0][r] = aR[q].x;
            As[b][kc + 1][r] = aR[q].y;
            As[b][kc + 2][r] = aR[q].z;
            As[b][kc + 3][r] = aR[q].w;
        }
#pragma unroll
        for (int q = 0; q < 4; q++) {
            int id = tid + q * 128;
            ((float4*)Ws[b])[id] = wR[q];
        }
    };

    loadT(0);
    stsT(0);
    __syncthreads();

    for (int kt = 0; kt < 8; kt++) {
        if (kt < 7) loadT(kt + 1);
        int b = kt & 1;
#pragma unroll
        for (int k = 0; k < 16; k++) {
            float4 a0 = *(float4*)&As[b][k][ty * 8];
            float4 a1 = *(float4*)&As[b][k][ty * 8 + 4];
            ulonglong2 w0 = *(ulonglong2*)&Ws[b][k][tx * 8];
            ulonglong2 w1 = *(ulonglong2*)&Ws[b][k][tx * 8 + 4];
            unsigned long long wp[4] = {w0.x, w0.y, w1.x, w1.y};
            float av[8] = {a0.x, a0.y, a0.z, a0.w, a1.x, a1.y, a1.z, a1.w};
#pragma unroll
            for (int i = 0; i < 8; i++) {
                unsigned long long ap;
                asm("mov.b64 %0, {%1, %1};" : "=l"(ap) : "r"(__float_as_uint(av[i])));
#pragma unroll
                for (int j = 0; j < 4; j++) {
                    asm("fma.rn.f32x2 %0, %1, %2, %0;"
                        : "+l"(acc[i][j]) : "l"(ap), "l"(wp[j]));
                }
            }
        }
        if (kt < 7) {
            stsT((kt + 1) & 1);
            __syncthreads();
        }
    }

#pragma unroll
    for (int i = 0; i < 8; i++) {
        int grow = row0 + ty * 8 + i;
        if (grow < M) {
            float o[8];
#pragma unroll
            for (int j = 0; j < 4; j++) {
                unsigned int lo, hi;
                asm("mov.b64 {%0, %1}, %2;" : "=r"(lo), "=r"(hi) : "l"(acc[i][j]));
                o[2 * j] = __uint_as_float(lo);
                o[2 * j + 1] = __uint_as_float(hi);
            }
            *(float4*)&C[(size_t)grow * DD + tx * 8] = make_float4(o[0], o[1], o[2], o[3]);
            *(float4*)&C[(size_t)grow * DD + tx * 8 + 4] = make_float4(o[4], o[5], o[6], o[7]);
        }
    }
}

// ================= gather aggregation: one warp per dst node =================
template <int FINAL>
__global__ void k_agg(const float* __restrict__ b,
                      const int* __restrict__ batch,
                      float* __restrict__ out) {
    int warp = (blockIdx.x * blockDim.x + threadIdx.x) >> 5;
    int lane = threadIdx.x & 31;
    if (warp >= NN) return;
    int d = warp;

    float di = g_dinv[d];
    float n2 = di * di;
    float4 bb = ((const float4*)b)[lane];
    float4 v = ((const float4*)g_tmp)[d * 32 + lane];
    float4 acc;
    acc.x = fmaf(v.x, n2, bb.x); acc.y = fmaf(v.y, n2, bb.y);
    acc.z = fmaf(v.z, n2, bb.z); acc.w = fmaf(v.w, n2, bb.w);

    int idx = g_rowptr[d];
    int end = g_rowptr[d + 1];
    for (; idx + 1 < end; idx += 2) {
        int2 c0 = g_csr[idx];
        int2 c1 = g_csr[idx + 1];
        float n0 = __int_as_float(c0.y);
        float n1 = __int_as_float(c1.y);
        float4 u0 = ((const float4*)g_tmp)[c0.x * 32 + lane];
        float4 u1 = ((const float4*)g_tmp)[c1.x * 32 + lane];
        acc.x = fmaf(u0.x, n0, acc.x); acc.y = fmaf(u0.y, n0, acc.y);
        acc.z = fmaf(u0.z, n0, acc.z); acc.w = fmaf(u0.w, n0, acc.w);
        acc.x = fmaf(u1.x, n1, acc.x); acc.y = fmaf(u1.y, n1, acc.y);
        acc.z = fmaf(u1.z, n1, acc.z); acc.w = fmaf(u1.w, n1, acc.w);
    }
    if (idx < end) {
        int2 c = g_csr[idx];
        float nm = __int_as_float(c.y);
        float4 u = ((const float4*)g_tmp)[c.x * 32 + lane];
        acc.x = fmaf(u.x, nm, acc.x); acc.y = fmaf(u.y, nm, acc.y);
        acc.z = fmaf(u.z, nm, acc.z); acc.w = fmaf(u.w, nm, acc.w);
    }

    if (FINAL) {
        acc.x = fmaxf(acc.x, 0.f); acc.y = fmaxf(acc.y, 0.f);
        acc.z = fmaxf(acc.z, 0.f); acc.w = fmaxf(acc.w, 0.f);
        int g = batch[d];
        float* p = &out[g * DD + lane * 4];
        asm volatile("red.global.add.v4.f32 [%0], {%1, %2, %3, %4};"
                     :: "l"(p), "f"(acc.x), "f"(acc.y), "f"(acc.z), "f"(acc.w)
                     : "memory");
    } else {
        ((float4*)g_h)[d * 32 + lane] = acc;
    }
}

__global__ void k_pool_div(float* __restrict__ out) {
    int i = blockIdx.x * blockDim.x + threadIdx.x;
    if (i < NG * DD) out[i] /= fmaxf(g_cnt[i >> 7], 1.0f);
}

// ================= launch =================
extern "C" void kernel_launch(void* const* d_in, const int* in_sizes, int n_in,
                              void* d_out, int out_size) {
    const float* x = (const float*)d_in[0];
    const int* ei = (const int*)d_in[1];      // int32 (JAX x64 disabled)
    const int* batch = (const int*)d_in[2];
    const float* W0 = (const float*)d_in[3];
    const float* b0 = (const float*)d_in[4];
    const float* W1 = (const float*)d_in[5];
    const float* b1 = (const float*)d_in[6];
    const float* W2 = (const float*)d_in[7];
    const float* b2 = (const float*)d_in[8];
    float* out = (float*)d_out;

    float* tmp; cudaGetSymbolAddress((void**)&tmp, g_tmp);
    float* h;   cudaGetSymbolAddress((void**)&h, g_h);

    const int TB = 256;
    int nodeB = (NN + TB - 1) / TB;
    int edgeB = (EE + TB - 1) / TB;
    int gemmB = (NN + 63) / 64;
    int aggB = (NN * 32 + TB - 1) / TB;

    // ---- graph preprocessing (once) ----
    k_zero<<<(NG * DD + TB - 1) / TB > nodeB ? (NG * DD + TB - 1) / TB : nodeB, TB>>>(out);
    k_deg_count<<<edgeB, TB>>>(ei);
    k_scan1<<<NCHUNK, SCAN_CHUNK>>>();
    k_scan2<<<1, 64>>>();
    k_scan3<<<nodeB, TB>>>();
    k_csr_fill<<<edgeB, TB>>>(ei);
    k_cnt<<<1, 64>>>(batch);

    // ---- layer 0 ----
    k_gemm<<<gemmB, 128>>>(x, W0, tmp, NN, 0);
    k_agg<0><<<aggB, TB>>>(b0, batch, out);
    // ---- layer 1 ----
    k_gemm<<<gemmB, 128>>>(h, W1, tmp, NN, 1);
    k_agg<0><<<aggB, TB>>>(b1, batch, out);
    // ---- layer 2 (fused relu + pool) ----
    k_gemm<<<gemmB, 128>>>(h, W2, tmp, NN, 1);
    k_agg<1><<<aggB, TB>>>(b2, batch, out);

    k_pool_div<<<(NG * DD + TB - 1) / TB, TB>>>(out);
}

// round 8
// speedup vs baseline: 1.7141x; 1.0483x over previous
#include <cuda_runtime.h>
#include <cuda_bf16.h>
#include <cstdint>

#define NN 50000
#define EE 800000
#define DD 128
#define NG 64
#define SCAN_CHUNK 1024
#define NCHUNK ((NN + SCAN_CHUNK - 1) / SCAN_CHUNK)   // 49

// -------- scratch (device globals: no allocation allowed) --------
__device__ __align__(16) float g_tmp[NN * DD];   // h @ W result
__device__ __align__(16) float g_h[NN * DD];     // aggregated layer output
__device__ __align__(16) float g_dinv[NN];       // rsqrt(degree)
__device__ __align__(16) float g_cnt[NG];        // pool counts
__device__ __align__(16) int   g_degi[NN];       // int in-degree (no self loop)
__device__ __align__(16) int   g_rowptr[NN + 1]; // CSR row pointers (by dst)
__device__ __align__(16) int   g_cursor[NN];     // scatter cursors
__device__ __align__(16) int2  g_csr[EE];        // {src, norm-as-int}
__device__ __align__(16) int   g_bsum[NCHUNK];   // per-chunk totals (from scan1)

// ================= prep =================
__global__ void k_zero(float* __restrict__ out) {
    int i = blockIdx.x * blockDim.x + threadIdx.x;
    if (i < NN) g_degi[i] = 0;
    if (i < NG * DD) out[i] = 0.f;
}

__global__ void k_deg_count(const int* __restrict__ ei) {
    int e = blockIdx.x * blockDim.x + threadIdx.x;
    if (e < EE) atomicAdd(&g_degi[ei[EE + e]], 1);
}

// ---- scan phase 1: per-chunk exclusive scan into rowptr, chunk total to g_bsum ----
__global__ void k_scan1() {
    __shared__ int wsum[32];
    int tid = threadIdx.x, lane = tid & 31, wd = tid >> 5;
    int i = blockIdx.x * SCAN_CHUNK + tid;
    int v = (i < NN) ? g_degi[i] : 0;
    int x = v;
#pragma unroll
    for (int o = 1; o < 32; o <<= 1) {
        int y = __shfl_up_sync(0xffffffffu, x, o);
        if (lane >= o) x += y;
    }
    if (lane == 31) wsum[wd] = x;
    __syncthreads();
    if (wd == 0) {
        int s = wsum[lane];
#pragma unroll
        for (int o = 1; o < 32; o <<= 1) {
            int y = __shfl_up_sync(0xffffffffu, s, o);
            if (lane >= o) s += y;
        }
        wsum[lane] = s;
    }
    __syncthreads();
    int excl = (wd ? wsum[wd - 1] : 0) + x - v;
    if (i < NN) g_rowptr[i] = excl;
    if (tid == SCAN_CHUNK - 1) g_bsum[blockIdx.x] = wsum[31];
}

// ---- scan phase 2+3 fused: each block re-derives the chunk-offset prefix locally,
//      writes rowptr/cursor/dinv; block 0 also computes pool counts (sorted batch). ----
__global__ void k_scan3(const int* __restrict__ batch) {
    __shared__ int pref[NCHUNK];
    int tid = threadIdx.x;
    if (tid == 0) {
        int run = 0;
#pragma unroll 1
        for (int j = 0; j < NCHUNK; j++) {
            int t = g_bsum[j];
            pref[j] = run;
            run += t;
        }
    }
    __syncthreads();
    int i = blockIdx.x * blockDim.x + tid;
    if (i < NN) {
        int rp = g_rowptr[i] + pref[i / SCAN_CHUNK];
        g_rowptr[i] = rp;
        g_cursor[i] = rp;
        g_dinv[i] = rsqrtf((float)(g_degi[i] + 1));
    }
    if (i == 0) g_rowptr[NN] = EE;
    if (blockIdx.x == 0 && tid < NG) {
        int g = tid;
        int lo = 0, hi = NN;
        while (lo < hi) { int m = (lo + hi) >> 1; if (batch[m] < g) lo = m + 1; else hi = m; }
        int start = lo;
        lo = 0; hi = NN;
        while (lo < hi) { int m = (lo + hi) >> 1; if (batch[m] <= g) lo = m + 1; else hi = m; }
        g_cnt[g] = (float)(lo - start);
    }
}

// ---- CSR fill: one 8B write per edge ----
__global__ void k_csr_fill(const int* __restrict__ ei) {
    int e = blockIdx.x * blockDim.x + threadIdx.x;
    if (e < EE) {
        int s = ei[e];
        int d = ei[EE + e];
        int pos = atomicAdd(&g_cursor[d], 1);
        float nm = g_dinv[s] * g_dinv[d];
        g_csr[pos] = make_int2(s, __float_as_int(nm));
    }
}

// ================= GEMM: C[M,128] = reluOpt(A)[M,128] @ W[128,128] =================
__global__ __launch_bounds__(128, 4)
void k_gemm(const float* __restrict__ A, const float* __restrict__ W,
            float* __restrict__ C, int M, int relu_in) {
    __shared__ float As[2][16][68];
    __shared__ float Ws[2][16][128];

    int tid = threadIdx.x;
    int tx = tid & 15;
    int ty = tid >> 4;
    int row0 = blockIdx.x * 64;

    unsigned long long acc[8][4];
#pragma unroll
    for (int i = 0; i < 8; i++)
#pragma unroll
        for (int j = 0; j < 4; j++) acc[i][j] = 0ull;

    float4 aR[2];
    float4 wR[4];

    auto loadT = [&](int kt) {
#pragma unroll
        for (int q = 0; q < 2; q++) {
            int id = tid + q * 128;
            int r = id >> 2;
            int kc = (id & 3) * 4;
            int grow = row0 + r;
            float4 v = make_float4(0.f, 0.f, 0.f, 0.f);
            if (grow < M) v = *(const float4*)&A[(size_t)grow * DD + kt * 16 + kc];
            if (relu_in) {
                v.x = fmaxf(v.x, 0.f); v.y = fmaxf(v.y, 0.f);
                v.z = fmaxf(v.z, 0.f); v.w = fmaxf(v.w, 0.f);
            }
            aR[q] = v;
        }
#pragma unroll
        for (int q = 0; q < 4; q++) {
            int id = tid + q * 128;
            wR[q] = ((const float4*)&W[kt * 16 * DD])[id];
        }
    };
    auto stsT = [&](int b) {
#pragma unroll
        for (int q = 0; q < 2; q++) {
            int id = tid + q * 128;
            int r = id >> 2;
            int kc = (id & 3) * 4;
            As[b][kc + 0][r] = aR[q].x;
            As[b][kc + 1][r] = aR[q].y;
            As[b][kc + 2][r] = aR[q].z;
            As[b][kc + 3][r] = aR[q].w;
        }
#pragma unroll
        for (int q = 0; q < 4; q++) {
            int id = tid + q * 128;
            ((float4*)Ws[b])[id] = wR[q];
        }
    };

    loadT(0);
    stsT(0);
    __syncthreads();

    for (int kt = 0; kt < 8; kt++) {
        if (kt < 7) loadT(kt + 1);
        int b = kt & 1;
#pragma unroll
        for (int k = 0; k < 16; k++) {
            float4 a0 = *(float4*)&As[b][k][ty * 8];
            float4 a1 = *(float4*)&As[b][k][ty * 8 + 4];
            ulonglong2 w0 = *(ulonglong2*)&Ws[b][k][tx * 8];
            ulonglong2 w1 = *(ulonglong2*)&Ws[b][k][tx * 8 + 4];
            unsigned long long wp[4] = {w0.x, w0.y, w1.x, w1.y};
            float av[8] = {a0.x, a0.y, a0.z, a0.w, a1.x, a1.y, a1.z, a1.w};
#pragma unroll
            for (int i = 0; i < 8; i++) {
                unsigned long long ap;
                asm("mov.b64 %0, {%1, %1};" : "=l"(ap) : "r"(__float_as_uint(av[i])));
#pragma unroll
                for (int j = 0; j < 4; j++) {
                    asm("fma.rn.f32x2 %0, %1, %2, %0;"
                        : "+l"(acc[i][j]) : "l"(ap), "l"(wp[j]));
                }
            }
        }
        if (kt < 7) {
            stsT((kt + 1) & 1);
            __syncthreads();
        }
    }

#pragma unroll
    for (int i = 0; i < 8; i++) {
        int grow = row0 + ty * 8 + i;
        if (grow < M) {
            float o[8];
#pragma unroll
            for (int j = 0; j < 4; j++) {
                unsigned int lo, hi;
                asm("mov.b64 {%0, %1}, %2;" : "=r"(lo), "=r"(hi) : "l"(acc[i][j]));
                o[2 * j] = __uint_as_float(lo);
                o[2 * j + 1] = __uint_as_float(hi);
            }
            *(float4*)&C[(size_t)grow * DD + tx * 8] = make_float4(o[0], o[1], o[2], o[3]);
            *(float4*)&C[(size_t)grow * DD + tx * 8 + 4] = make_float4(o[4], o[5], o[6], o[7]);
        }
    }
}

// ================= gather aggregation: one warp per dst node =================
template <int FINAL>
__global__ void k_agg(const float* __restrict__ b,
                      const int* __restrict__ batch,
                      float* __restrict__ out) {
    int warp = (blockIdx.x * blockDim.x + threadIdx.x) >> 5;
    int lane = threadIdx.x & 31;
    if (warp >= NN) return;
    int d = warp;

    float di = g_dinv[d];
    float n2 = di * di;
    float4 bb = ((const float4*)b)[lane];
    float4 v = ((const float4*)g_tmp)[d * 32 + lane];
    float4 acc;
    acc.x = fmaf(v.x, n2, bb.x); acc.y = fmaf(v.y, n2, bb.y);
    acc.z = fmaf(v.z, n2, bb.z); acc.w = fmaf(v.w, n2, bb.w);

    int idx = g_rowptr[d];
    int end = g_rowptr[d + 1];
    for (; idx + 1 < end; idx += 2) {
        int2 c0 = g_csr[idx];
        int2 c1 = g_csr[idx + 1];
        float n0 = __int_as_float(c0.y);
        float n1 = __int_as_float(c1.y);
        float4 u0 = ((const float4*)g_tmp)[c0.x * 32 + lane];
        float4 u1 = ((const float4*)g_tmp)[c1.x * 32 + lane];
        acc.x = fmaf(u0.x, n0, acc.x); acc.y = fmaf(u0.y, n0, acc.y);
        acc.z = fmaf(u0.z, n0, acc.z); acc.w = fmaf(u0.w, n0, acc.w);
        acc.x = fmaf(u1.x, n1, acc.x); acc.y = fmaf(u1.y, n1, acc.y);
        acc.z = fmaf(u1.z, n1, acc.z); acc.w = fmaf(u1.w, n1, acc.w);
    }
    if (idx < end) {
        int2 c = g_csr[idx];
        float nm = __int_as_float(c.y);
        float4 u = ((const float4*)g_tmp)[c.x * 32 + lane];
        acc.x = fmaf(u.x, nm, acc.x); acc.y = fmaf(u.y, nm, acc.y);
        acc.z = fmaf(u.z, nm, acc.z); acc.w = fmaf(u.w, nm, acc.w);
    }

    if (FINAL) {
        acc.x = fmaxf(acc.x, 0.f); acc.y = fmaxf(acc.y, 0.f);
        acc.z = fmaxf(acc.z, 0.f); acc.w = fmaxf(acc.w, 0.f);
        int g = batch[d];
        float* p = &out[g * DD + lane * 4];
        asm volatile("red.global.add.v4.f32 [%0], {%1, %2, %3, %4};"
                     :: "l"(p), "f"(acc.x), "f"(acc.y), "f"(acc.z), "f"(acc.w)
                     : "memory");
    } else {
        ((float4*)g_h)[d * 32 + lane] = acc;
    }
}

__global__ void k_pool_div(float* __restrict__ out) {
    int i = blockIdx.x * blockDim.x + threadIdx.x;
    if (i < NG * DD) out[i] /= fmaxf(g_cnt[i >> 7], 1.0f);
}

// ================= launch =================
extern "C" void kernel_launch(void* const* d_in, const int* in_sizes, int n_in,
                              void* d_out, int out_size) {
    const float* x = (const float*)d_in[0];
    const int* ei = (const int*)d_in[1];      // int32 (JAX x64 disabled)
    const int* batch = (const int*)d_in[2];
    const float* W0 = (const float*)d_in[3];
    const float* b0 = (const float*)d_in[4];
    const float* W1 = (const float*)d_in[5];
    const float* b1 = (const float*)d_in[6];
    const float* W2 = (const float*)d_in[7];
    const float* b2 = (const float*)d_in[8];
    float* out = (float*)d_out;

    float* tmp; cudaGetSymbolAddress((void**)&tmp, g_tmp);
    float* h;   cudaGetSymbolAddress((void**)&h, g_h);

    const int TB = 256;
    int nodeB = (NN + TB - 1) / TB;
    int edgeB = (EE + TB - 1) / TB;
    int gemmB = (NN + 63) / 64;
    int aggB = (NN * 32 + TB - 1) / TB;
    int zeroB = nodeB;  // NN/256 > NG*DD/256

    // second stream for layer-0 GEMM (independent of graph prep); event fork/join
    // keeps everything inside the captured graph.
    cudaStream_t s2;
    cudaStreamCreateWithFlags(&s2, cudaStreamNonBlocking);
    cudaEvent_t evFork, evJoin;
    cudaEventCreateWithFlags(&evFork, cudaEventDisableTiming);
    cudaEventCreateWithFlags(&evJoin, cudaEventDisableTiming);

    cudaEventRecord(evFork, 0);
    cudaStreamWaitEvent(s2, evFork, 0);
    // ---- layer-0 GEMM on s2, concurrent with prep ----
    k_gemm<<<gemmB, 128, 0, s2>>>(x, W0, tmp, NN, 0);
    cudaEventRecord(evJoin, s2);

    // ---- graph preprocessing on default stream ----
    k_zero<<<zeroB, TB>>>(out);
    k_deg_count<<<edgeB, TB>>>(ei);
    k_scan1<<<NCHUNK, SCAN_CHUNK>>>();
    k_scan3<<<nodeB, TB>>>(batch);
    k_csr_fill<<<edgeB, TB>>>(ei);

    cudaStreamWaitEvent(0, evJoin, 0);

    // ---- layer 0 aggregation ----
    k_agg<0><<<aggB, TB>>>(b0, batch, out);
    // ---- layer 1 ----
    k_gemm<<<gemmB, 128>>>(h, W1, tmp, NN, 1);
    k_agg<0><<<aggB, TB>>>(b1, batch, out);
    // ---- layer 2 (fused relu + pool) ----
    k_gemm<<<gemmB, 128>>>(h, W2, tmp, NN, 1);
    k_agg<1><<<aggB, TB>>>(b2, batch, out);

    k_pool_div<<<(NG * DD + TB - 1) / TB, TB>>>(out);
}